// round 3
// baseline (speedup 1.0000x reference)
#include <cuda_runtime.h>
#include <cuda_bf16.h>

// VQ lookup: z[N,510] f32, codebook[128,510] f32 -> z_q[N,510] f32
// dist2 = z_sq - 2*z.c + c_sq ; k = argmin ; out = codebook[k]
//
// Design: fp32 CUDA-core GEMM-like kernel using packed fma.rn.f32x2
// (128 MAC/cyc/SM vs 64 for scalar FFMA). Block = 64 rows x 128 codes,
// 256 threads, thread tile 8 rows x 4 codes, D streamed in 8 chunks of 64
// through shared memory. Argmin + gather fused in epilogue.

#define D_DIM   510
#define K_CODES 128
#define BM      64
#define DCHUNK  64
#define NCHUNK  8      // ceil(510/64) -> 512 padded with zeros
#define ZSTR    68     // smem row stride (floats): 68*4B = 272B = 17*16B, bank-safe
#define CSTR    68

#define SMEM_FLOATS (K_CODES*CSTR + BM*ZSTR + 8*BM + 8*BM + BM + BM)
#define SMEM_BYTES  (SMEM_FLOATS * 4)

__device__ float g_csq[K_CODES];

// ---------------------------------------------------------------------------
// c_sq[k] = sum_d codebook[k][d]^2   (128 blocks x 256 threads)
// ---------------------------------------------------------------------------
__global__ void csq_kernel(const float* __restrict__ cb) {
    int k = blockIdx.x;
    int tid = threadIdx.x;
    float s = 0.f;
    for (int d = tid; d < D_DIM; d += 256) {
        float v = cb[k * D_DIM + d];
        s = fmaf(v, v, s);
    }
    #pragma unroll
    for (int off = 16; off; off >>= 1)
        s += __shfl_xor_sync(0xffffffffu, s, off);
    __shared__ float red[8];
    if ((tid & 31) == 0) red[tid >> 5] = s;
    __syncthreads();
    if (tid == 0) {
        float t = 0.f;
        #pragma unroll
        for (int i = 0; i < 8; i++) t += red[i];
        g_csq[k] = t;
    }
}

// Packed dual-FMA: d.lo += a.lo*b.lo ; d.hi += a.hi*b.hi
__device__ __forceinline__ void fma2(unsigned long long& d,
                                     unsigned long long a,
                                     unsigned long long b) {
    asm("fma.rn.f32x2 %0, %1, %2, %0;" : "+l"(d) : "l"(a), "l"(b));
}

extern __shared__ float smem[];

__global__ __launch_bounds__(256, 2)
void vq_kernel(const float* __restrict__ z,
               const float* __restrict__ cb,
               float* __restrict__ out) {
    // smem carve
    float* cb_s  = smem;                         // 128*68
    float* z_s   = cb_s + K_CODES * CSTR;        // 64*68
    float* redv  = z_s + BM * ZSTR;              // 8*64
    int*   redk  = (int*)(redv + 8 * BM);        // 8*64
    float* zsq_s = (float*)(redk + 8 * BM);      // 64
    int*   kfin  = (int*)(zsq_s + BM);           // 64

    const int tid  = threadIdx.x;
    const int wid  = tid >> 5;
    const int lane = tid & 31;
    const int tr   = lane >> 2;   // 0..7 : row-group within warp
    const int tc   = lane & 3;    // 0..3 : code-group within warp
    const long long row0 = (long long)blockIdx.x * BM;

    unsigned long long acc[8][4];
    #pragma unroll
    for (int j = 0; j < 8; j++)
        #pragma unroll
        for (int cc = 0; cc < 4; cc++) acc[j][cc] = 0ull;

    float zsqp[8] = {0.f, 0.f, 0.f, 0.f, 0.f, 0.f, 0.f, 0.f};

    const float* zg = z + row0 * D_DIM;

    for (int ch = 0; ch < NCHUNK; ++ch) {
        __syncthreads();
        const int dbase = ch * DCHUNK;

        // load z tile: 64 rows x 32 float2 (coalesced), accumulate z_sq partials
        // load index li -> row = li>>5 = it*8 + wid (fixed row set per warp)
        #pragma unroll
        for (int it = 0; it < 8; ++it) {
            int li = it * 256 + tid;
            int r  = li >> 5;
            int dd = (li & 31) * 2;
            int gd = dbase + dd;
            float2 v = make_float2(0.f, 0.f);
            if (gd < D_DIM) v = *(const float2*)(zg + (long long)r * D_DIM + gd);
            *(float2*)(z_s + r * ZSTR + dd) = v;
            zsqp[it] = fmaf(v.x, v.x, fmaf(v.y, v.y, zsqp[it]));
        }
        // load codebook tile: 128 rows x 32 float2 (L2-hot)
        #pragma unroll
        for (int it = 0; it < 16; ++it) {
            int li = it * 256 + tid;
            int c  = li >> 5;
            int dd = (li & 31) * 2;
            int gd = dbase + dd;
            float2 v = make_float2(0.f, 0.f);
            if (gd < D_DIM) v = *(const float2*)(cb + c * D_DIM + gd);
            *(float2*)(cb_s + c * CSTR + dd) = v;
        }
        __syncthreads();

        const float* zp = z_s + tr * ZSTR;                 // rows tr + 8j
        const float* cp = cb_s + (wid * 16 + tc) * CSTR;   // codes w*16 + cc*4 + tc

        #pragma unroll 4
        for (int step = 0; step < 16; ++step) {
            const int d2 = step * 4;
            ulonglong2 cfr[4];
            #pragma unroll
            for (int cc = 0; cc < 4; ++cc)
                cfr[cc] = *(const ulonglong2*)(cp + cc * (4 * CSTR) + d2);
            #pragma unroll
            for (int j = 0; j < 8; ++j) {
                ulonglong2 zv = *(const ulonglong2*)(zp + j * (8 * ZSTR) + d2);
                #pragma unroll
                for (int cc = 0; cc < 4; ++cc) {
                    fma2(acc[j][cc], zv.x, cfr[cc].x);
                    fma2(acc[j][cc], zv.y, cfr[cc].y);
                }
            }
        }
    }

    // z_sq: reduce per-warp partials (lane holds a 2-col slice of row it*8+wid)
    #pragma unroll
    for (int it = 0; it < 8; ++it) {
        float s = zsqp[it];
        #pragma unroll
        for (int off = 16; off; off >>= 1)
            s += __shfl_xor_sync(0xffffffffu, s, off);
        if (lane == 0) zsq_s[it * 8 + wid] = s;
    }
    __syncthreads();

    float csqr[4];
    #pragma unroll
    for (int cc = 0; cc < 4; ++cc)
        csqr[cc] = g_csq[wid * 16 + cc * 4 + tc];

    // per-thread argmin over its 4 codes, then shuffle-reduce over tc
    #pragma unroll
    for (int j = 0; j < 8; ++j) {
        const int r = tr + 8 * j;
        const float zs = zsq_s[r];
        float bv = 3.4e38f;
        int   bk = 0;
        #pragma unroll
        for (int cc = 0; cc < 4; ++cc) {
            unsigned long long a = acc[j][cc];
            float lo = __uint_as_float((unsigned)a);
            float hi = __uint_as_float((unsigned)(a >> 32));
            float dot = lo + hi;
            float d2v = fmaf(-2.f, dot, zs) + csqr[cc];   // (z_sq - 2*dot) + c_sq
            int c = wid * 16 + cc * 4 + tc;
            if (d2v < bv || (d2v == bv && c < bk)) { bv = d2v; bk = c; }
        }
        #pragma unroll
        for (int off = 1; off <= 2; off <<= 1) {
            float ov = __shfl_xor_sync(0xffffffffu, bv, off);
            int   ok = __shfl_xor_sync(0xffffffffu, bk, off);
            if (ov < bv || (ov == bv && ok < bk)) { bv = ov; bk = ok; }
        }
        if (tc == 0) { redv[wid * BM + r] = bv; redk[wid * BM + r] = bk; }
    }
    __syncthreads();

    // final argmin across the 8 warps' code groups
    if (tid < BM) {
        float bv = redv[tid];
        int   bk = redk[tid];
        #pragma unroll
        for (int w = 1; w < 8; ++w) {
            float ov = redv[w * BM + tid];
            int   ok = redk[w * BM + tid];
            if (ov < bv || (ov == bv && ok < bk)) { bv = ov; bk = ok; }
        }
        kfin[tid] = bk;
    }
    __syncthreads();

    // gather: out[row] = codebook[kfin[row]]  (codebook rows are L2-hot)
    if (tid < 255) {
        const int dpos = tid * 2;             // 255 float2 = 510 floats
        float* ob = out + row0 * D_DIM + dpos;
        #pragma unroll 8
        for (int r = 0; r < BM; ++r) {
            int k = kfin[r];
            float2 v = *(const float2*)(cb + k * D_DIM + dpos);
            *(float2*)(ob + (long long)r * D_DIM) = v;
        }
    }
}

extern "C" void kernel_launch(void* const* d_in, const int* in_sizes, int n_in,
                              void* d_out, int out_size) {
    const float* z  = (const float*)d_in[0];
    const float* cb = (const float*)d_in[1];
    float* out = (float*)d_out;

    cudaFuncSetAttribute(vq_kernel, cudaFuncAttributeMaxDynamicSharedMemorySize,
                         SMEM_BYTES);

    const int n_rows = in_sizes[0] / D_DIM;       // 131072
    const int nblocks = n_rows / BM;              // 2048

    csq_kernel<<<K_CODES, 256>>>(cb);
    vq_kernel<<<nblocks, 256, SMEM_BYTES>>>(z, cb, out);
}